// round 4
// baseline (speedup 1.0000x reference)
#include <cuda_runtime.h>

#define H 32
#define NL 4
#define TT 64
#define NB 16            // batches per chunk
#define NCH 8            // chunks per CTA
#define BPC (NB * NCH)   // 128 batches per CTA
#define THREADS 512

typedef unsigned long long u64;

// Pre-transposed, k-pair-packed weights (u64 = f32x2 over k=2m,2m+1):
__device__ u64   gWhh[NL * 4 * 32 * 16];        // [l][g][j][m]
__device__ u64   gWih[(NL - 1) * 4 * 32 * 16];  // [l-1][g][j][m]
__device__ u64   gWih0[4 * 32];                 // [g][j] (k=0,1)
__device__ float gBias[NL * 4 * 32];            // [l][g][j], b_ih+b_hh
__device__ float gWlin[H];
__device__ float gBlin;

__device__ __forceinline__ u64 pk2(float a, float b) {
    u64 r; asm("mov.b64 %0, {%1, %2};" : "=l"(r) : "f"(a), "f"(b)); return r;
}
__device__ __forceinline__ float2 upk(u64 v) {
    float2 r; asm("mov.b64 {%0, %1}, %2;" : "=f"(r.x), "=f"(r.y) : "l"(v)); return r;
}
// Blackwell packed fp32x2 FMA.
__device__ __forceinline__ u64 ffma2(u64 a, u64 b, u64 c) {
    u64 d; asm("fma.rn.f32x2 %0, %1, %2, %3;" : "=l"(d) : "l"(a), "l"(b), "l"(c)); return d;
}

__global__ void prep_kernel(const float* __restrict__ W_ih0, const float* __restrict__ W_ih,
                            const float* __restrict__ W_hh, const float* __restrict__ b_ih,
                            const float* __restrict__ b_hh, const float* __restrict__ W_lin,
                            const float* __restrict__ b_lin) {
    int i = blockIdx.x * blockDim.x + threadIdx.x;
    // gWhh floats: [l][g][j][m][c2]  (c2=0 -> k=2m low half)
    if (i < NL * 4 * 32 * 16 * 2) {
        int c2 = i & 1, m = (i >> 1) & 15, j = (i >> 5) & 31, g = (i >> 10) & 3, l = i >> 12;
        int k = 2 * m + c2;
        ((float*)gWhh)[i] = W_hh[l * 4096 + (g * 32 + j) * 32 + k];
    }
    if (i < (NL - 1) * 4 * 32 * 16 * 2) {
        int c2 = i & 1, m = (i >> 1) & 15, j = (i >> 5) & 31, g = (i >> 10) & 3, l = i >> 12;
        int k = 2 * m + c2;
        ((float*)gWih)[i] = W_ih[l * 4096 + (g * 32 + j) * 32 + k];
    }
    if (i < 4 * 32 * 2) {
        int c2 = i & 1, j = (i >> 1) & 31, g = i >> 6;
        ((float*)gWih0)[i] = W_ih0[(g * 32 + j) * 2 + c2];
    }
    if (i < NL * 4 * 32) {
        int j = i & 31, g = (i >> 5) & 3, l = i >> 7;
        gBias[i] = b_ih[l * 128 + g * 32 + j] + b_hh[l * 128 + g * 32 + j];
    }
    if (i < H) gWlin[i] = W_lin[i];
    if (i == 0) gBlin = b_lin[0];
}

__global__ void __launch_bounds__(THREADS, 1)
lstm_kernel(const float* __restrict__ x, float* __restrict__ out) {
    __shared__ __align__(16) float hbuf[2][NL][NB][H];

    const int tid  = threadIdx.x;
    const int wid  = tid >> 5;
    const int lane = tid & 31;
    const int jh   = wid & 3;     // j-group (also fixes SMSP -> layer balance per SMSP)
    const int l    = wid >> 2;    // layer of this warp
    const int g    = lane >> 3;   // gate
    const int j    = jh * 8 + (lane & 7);
    const int ctaBase = blockIdx.x * BPC;

    // ---- load this lane's weights into registers (stay resident all kernel) ----
    u64 whh[16], wih[16], wih0 = 0ull;
    {
        const u64* ph = &gWhh[((l * 4 + g) * 32 + j) * 16];
#pragma unroll
        for (int m = 0; m < 16; ++m) whh[m] = ph[m];
        if (l > 0) {
            const u64* pi = &gWih[(((l - 1) * 4 + g) * 32 + j) * 16];
#pragma unroll
            for (int m = 0; m < 16; ++m) wih[m] = pi[m];
        } else {
            wih0 = gWih0[g * 32 + j];
#pragma unroll
            for (int m = 0; m < 16; ++m) wih[m] = 0ull;
        }
    }
    const float bias = gBias[(l * 4 + g) * 32 + j];

    // Uniform activation: sigmoid and tanh both as fma(S1, 1/(1+exp2(M*v)), S0)
    const float LOG2E = 1.4426950408889634f;
    const float Ma  = (g == 2) ? -2.f * LOG2E : -LOG2E;
    const float S1a = (g == 2) ? 2.f : 1.f;
    const float S0a = (g == 2) ? -1.f : 0.f;
    const float MT  = -2.f * LOG2E;   // for tanh(c)

    const float wl = gWlin[lane];

    float c[NB];
#pragma unroll
    for (int b = 0; b < NB; ++b) c[b] = 0.f;

    const int UTOT = NCH * TT + NL;   // +NL: drain + final head tick
    for (int u = 0; u < UTOT; ++u) {
        const int p   = u & 1;        // read buffer parity
        const int tau = u - l;

        // ---- head: layer-3 warps emit outputs for a chunk finished last tick ----
        if (l == 3) {
            int tph = u - 1 - 3;
            if (tph >= 0 && (tph & 63) == 63) {
                int cprev = tph >> 6;
#pragma unroll
                for (int q = 0; q < 4; ++q) {
                    int b = jh * 4 + q;
                    float s = hbuf[p][3][b][lane] * wl;
#pragma unroll
                    for (int off = 16; off > 0; off >>= 1)
                        s += __shfl_xor_sync(0xffffffffu, s, off);
                    if (lane == 0) {
                        float v = s + gBlin;
                        float e = exp2f(-v * LOG2E);
                        out[ctaBase + cprev * NB + b] = __fdividef(1.f, 1.f + e);
                    }
                }
            }
        }

        if (tau >= 0 && tau < NCH * TT) {
            const int t  = tau & 63;
            const int ch = tau >> 6;
            const float* hin = &hbuf[p][(l == 0) ? 0 : (l - 1)][0][0];
            const float* hpr = &hbuf[p][l][0][0];
            float*       hw  = &hbuf[p ^ 1][l][0][0];
            const float* xb  = x + (size_t)(ctaBase + ch * NB) * 192 + t;

#pragma unroll 4
            for (int b = 0; b < NB; ++b) {
                u64 a0 = pk2(bias, 0.f), a1 = 0ull;
                if (l == 0) {
                    float x0 = __ldg(xb + (size_t)b * 192);        // feat 0
                    float x1 = __ldg(xb + (size_t)b * 192 + 64);   // feat 1
                    a0 = ffma2(pk2(x0, x1), wih0, a0);
                } else {
                    const ulonglong2* hi2 = (const ulonglong2*)(hin + b * H);
#pragma unroll
                    for (int m2 = 0; m2 < 8; ++m2) {
                        ulonglong2 v = hi2[m2];                    // broadcast LDS.128
                        a0 = ffma2(v.x, wih[2 * m2],     a0);
                        a1 = ffma2(v.y, wih[2 * m2 + 1], a1);
                    }
                }
                if (t != 0) {
                    const ulonglong2* hp2 = (const ulonglong2*)(hpr + b * H);
#pragma unroll
                    for (int m2 = 0; m2 < 8; ++m2) {
                        ulonglong2 v = hp2[m2];
                        a0 = ffma2(v.x, whh[2 * m2],     a0);
                        a1 = ffma2(v.y, whh[2 * m2 + 1], a1);
                    }
                }
                float2 f0 = upk(a0), f1 = upk(a1);
                float val = (f0.x + f1.x) + (f0.y + f1.y);

                // activation for this lane's gate (uniform code path)
                float e = exp2f(val * Ma);
                float r = __fdividef(1.f, 1.f + e);
                float a = fmaf(S1a, r, S0a);

                // gather i,f,g,o into g==0 lanes
                float af_ = __shfl_down_sync(0xffffffffu, a, 8);
                float ag_ = __shfl_down_sync(0xffffffffu, a, 16);
                float ao_ = __shfl_down_sync(0xffffffffu, a, 24);
                if (g == 0) {
                    float cold = (t == 0) ? 0.f : c[b];
                    float cn   = fmaf(af_, cold, a * ag_);
                    c[b] = cn;
                    float e2 = exp2f(cn * MT);
                    float th = fmaf(2.f, __fdividef(1.f, 1.f + e2), -1.f);
                    hw[b * H + j] = ao_ * th;
                }
            }
        }
        __syncthreads();   // tick boundary (all 16 warps)
    }
}

extern "C" void kernel_launch(void* const* d_in, const int* in_sizes, int n_in,
                              void* d_out, int out_size) {
    const float* x     = (const float*)d_in[0];
    const float* W_ih0 = (const float*)d_in[1];
    const float* W_ih  = (const float*)d_in[2];
    const float* W_hh  = (const float*)d_in[3];
    const float* b_ih  = (const float*)d_in[4];
    const float* b_hh  = (const float*)d_in[5];
    const float* W_lin = (const float*)d_in[6];
    const float* b_lin = (const float*)d_in[7];

    prep_kernel<<<64, 256>>>(W_ih0, W_ih, W_hh, b_ih, b_hh, W_lin, b_lin);

    int B = in_sizes[0] / (3 * TT);     // 16384
    int blocks = B / BPC;               // 128 CTAs, single wave
    lstm_kernel<<<blocks, THREADS>>>(x, (float*)d_out);
}

// round 5
// speedup vs baseline: 2.0975x; 2.0975x over previous
#include <cuda_runtime.h>

#define NL 4
#define H 32
#define TT 64
#define NP 8               // batch pairs per CTA -> 16 batches
#define THREADS 64         // warpA (gates i,f) + warpB (gates g,o)

typedef unsigned long long u64;

// Weight layout per gate-pair: [l][k2][j] float4 = (g0[2k2], g1[2k2], g0[2k2+1], g1[2k2+1])
__device__ float4 gWAhh[NL][16][32];       // gates (i,f)
__device__ float4 gWBhh[NL][16][32];       // gates (g,o)
__device__ float4 gWAih[NL - 1][16][32];
__device__ float4 gWBih[NL - 1][16][32];
__device__ float4 gWAih0[32];              // (i[k0], f[k0], i[k1], f[k1]) per j
__device__ float4 gWBih0[32];
__device__ float2 gBiasA[NL][32];          // (b_i, b_f)
__device__ float2 gBiasB[NL][32];          // (b_g, b_o)
__device__ float  gWlin[H];
__device__ float  gBlin;

__device__ __forceinline__ u64 pk2(float a, float b) {
    u64 r; asm("mov.b64 %0, {%1, %2};" : "=l"(r) : "f"(a), "f"(b)); return r;
}
__device__ __forceinline__ u64 pk2(float a) { return pk2(a, a); }
__device__ __forceinline__ float2 upk(u64 v) {
    float2 r; asm("mov.b64 {%0, %1}, %2;" : "=f"(r.x), "=f"(r.y) : "l"(v)); return r;
}
// Blackwell packed fp32x2 FMA.
__device__ __forceinline__ u64 ffma2(u64 a, u64 b, u64 c) {
    u64 d; asm("fma.rn.f32x2 %0, %1, %2, %3;" : "=l"(d) : "l"(a), "l"(b), "l"(c)); return d;
}

__device__ __forceinline__ float sigm(float v) {
    return __fdividef(1.0f, 1.0f + __expf(-v));
}
__device__ __forceinline__ float tanh_(float v) {
    return __fdividef(2.0f, 1.0f + __expf(-2.0f * v)) - 1.0f;
}

// acc{0,1}[p] += sum_k W{g0,g1}[k][j] * h[pair p][k]; h stored as float2(b_even,b_odd) per k.
__device__ __forceinline__ void mat_acc(const float4* __restrict__ wp,
                                        const float2* __restrict__ hrow,
                                        u64 acc0[NP], u64 acc1[NP]) {
#pragma unroll 2
    for (int k2 = 0; k2 < 16; ++k2) {
        float4 w = wp[k2 * 32];                     // LDG.128, coalesced over j
        u64 w00 = pk2(w.x), w10 = pk2(w.y);         // gates at k=2k2
        u64 w01 = pk2(w.z), w11 = pk2(w.w);         // gates at k=2k2+1
#pragma unroll
        for (int p = 0; p < NP; ++p) {
            float4 hv = *(const float4*)(hrow + p * H + 2 * k2);   // LDS.128 broadcast
            u64 v0 = pk2(hv.x, hv.y), v1 = pk2(hv.z, hv.w);
            acc0[p] = ffma2(v0, w00, acc0[p]);
            acc1[p] = ffma2(v0, w10, acc1[p]);
            acc0[p] = ffma2(v1, w01, acc0[p]);
            acc1[p] = ffma2(v1, w11, acc1[p]);
        }
    }
}

__global__ void prep_kernel(const float* __restrict__ W_ih0, const float* __restrict__ W_ih,
                            const float* __restrict__ W_hh, const float* __restrict__ b_ih,
                            const float* __restrict__ b_hh, const float* __restrict__ W_lin,
                            const float* __restrict__ b_lin) {
    int i = blockIdx.x * blockDim.x + threadIdx.x;
    // hh: 8192 floats each.  c: component of float4. g=c&1 (+2 for B), k=2*k2+(c>>1)
    if (i < NL * 16 * 32 * 4) {
        int c = i & 3, j = (i >> 2) & 31, k2 = (i >> 7) & 15, l = i >> 11;
        int k = 2 * k2 + (c >> 1);
        ((float*)gWAhh)[i] = W_hh[l * 4096 + (((c & 1) * 32) + j) * 32 + k];
        ((float*)gWBhh)[i] = W_hh[l * 4096 + (((2 + (c & 1)) * 32) + j) * 32 + k];
    }
    if (i < (NL - 1) * 16 * 32 * 4) {
        int c = i & 3, j = (i >> 2) & 31, k2 = (i >> 7) & 15, l = i >> 11;
        int k = 2 * k2 + (c >> 1);
        ((float*)gWAih)[i] = W_ih[l * 4096 + (((c & 1) * 32) + j) * 32 + k];
        ((float*)gWBih)[i] = W_ih[l * 4096 + (((2 + (c & 1)) * 32) + j) * 32 + k];
    }
    if (i < 32 * 4) {
        int c = i & 3, j = (i >> 2) & 31;
        int k = c >> 1;
        ((float*)gWAih0)[i] = W_ih0[(((c & 1) * 32) + j) * 2 + k];
        ((float*)gWBih0)[i] = W_ih0[(((2 + (c & 1)) * 32) + j) * 2 + k];
    }
    if (i < NL * 32 * 2) {
        int c = i & 1, j = (i >> 1) & 31, l = i >> 6;
        ((float*)gBiasA)[i] = b_ih[l * 128 + c * 32 + j] + b_hh[l * 128 + c * 32 + j];
        ((float*)gBiasB)[i] = b_ih[l * 128 + (2 + c) * 32 + j] + b_hh[l * 128 + (2 + c) * 32 + j];
    }
    if (i < H) gWlin[i] = W_lin[i];
    if (i == 0) gBlin = b_lin[0];
}

__global__ void __launch_bounds__(THREADS, 7)
lstm_kernel(const float* __restrict__ x, float* __restrict__ out) {
    __shared__ __align__(16) float2 hst[NL][NP][H];   // h, packed float2(b0,b1) per k
    __shared__ __align__(16) float2 cst[NL][NP][H];   // c state (warpB)
    __shared__ __align__(16) float4 sAB[NP][H];       // (si0,si1,sf0,sf1) exchange A->B

    const int j    = threadIdx.x & 31;
    const int wb   = threadIdx.x >> 5;    // 0 = (i,f), 1 = (g,o)
    const int base = blockIdx.x * (NP * 2);

    // per-warp bias (own two gates)
    float2 bias[NL];
#pragma unroll
    for (int l = 0; l < NL; ++l)
        bias[l] = wb ? gBiasB[l][j] : gBiasA[l][j];

    const float* xp = x + (size_t)base * 192;

#pragma unroll 1
    for (int t = 0; t < TT; ++t) {
        u64 acc0[NP], acc1[NP];

        // =============== layer 0 ===============
        {
            float4 w0 = wb ? gWBih0[j] : gWAih0[j];
            u64 wg00 = pk2(w0.x), wg10 = pk2(w0.y), wg01 = pk2(w0.z), wg11 = pk2(w0.w);
            u64 b0v = pk2(bias[0].x), b1v = pk2(bias[0].y);
#pragma unroll
            for (int p = 0; p < NP; ++p) {
                const float* xq = xp + (size_t)(2 * p) * 192 + t;
                u64 vx0 = pk2(__ldg(xq),      __ldg(xq + 192));        // feat 0, b0/b1
                u64 vx1 = pk2(__ldg(xq + 64), __ldg(xq + 256));        // feat 1
                acc0[p] = ffma2(vx0, wg00, b0v);
                acc1[p] = ffma2(vx0, wg10, b1v);
                acc0[p] = ffma2(vx1, wg01, acc0[p]);
                acc1[p] = ffma2(vx1, wg11, acc1[p]);
            }
            if (t) mat_acc(wb ? &gWBhh[0][0][j] : &gWAhh[0][0][j], &hst[0][0][0], acc0, acc1);
        }
        // gate combine for layer 0
        if (wb == 0) {
#pragma unroll
            for (int p = 0; p < NP; ++p) {
                float2 ai = upk(acc0[p]), af = upk(acc1[p]);
                sAB[p][j] = make_float4(sigm(ai.x), sigm(ai.y), sigm(af.x), sigm(af.y));
            }
        }
        __syncthreads();
        if (wb == 1) {
#pragma unroll
            for (int p = 0; p < NP; ++p) {
                float2 ag = upk(acc0[p]), ao = upk(acc1[p]);
                float tg0 = tanh_(ag.x), tg1 = tanh_(ag.y);
                float so0 = sigm(ao.x),  so1 = sigm(ao.y);
                float4 s = sAB[p][j];
                float2 cold = t ? cst[0][p][j] : make_float2(0.f, 0.f);
                float c0 = fmaf(s.z, cold.x, s.x * tg0);
                float c1 = fmaf(s.w, cold.y, s.y * tg1);
                cst[0][p][j] = make_float2(c0, c1);
                hst[0][p][j] = make_float2(so0 * tanh_(c0), so1 * tanh_(c1));
            }
        }
        __syncthreads();

        // =============== layers 1..3 ===============
#pragma unroll
        for (int l = 1; l < NL; ++l) {
            u64 b0v = pk2(bias[l].x), b1v = pk2(bias[l].y);
#pragma unroll
            for (int p = 0; p < NP; ++p) { acc0[p] = b0v; acc1[p] = b1v; }
            mat_acc(wb ? &gWBih[l - 1][0][j] : &gWAih[l - 1][0][j], &hst[l - 1][0][0], acc0, acc1);
            if (t) mat_acc(wb ? &gWBhh[l][0][j] : &gWAhh[l][0][j], &hst[l][0][0], acc0, acc1);

            if (wb == 0) {
#pragma unroll
                for (int p = 0; p < NP; ++p) {
                    float2 ai = upk(acc0[p]), af = upk(acc1[p]);
                    sAB[p][j] = make_float4(sigm(ai.x), sigm(ai.y), sigm(af.x), sigm(af.y));
                }
            }
            __syncthreads();
            if (wb == 1) {
#pragma unroll
                for (int p = 0; p < NP; ++p) {
                    float2 ag = upk(acc0[p]), ao = upk(acc1[p]);
                    float tg0 = tanh_(ag.x), tg1 = tanh_(ag.y);
                    float so0 = sigm(ao.x),  so1 = sigm(ao.y);
                    float4 s = sAB[p][j];
                    float2 cold = t ? cst[l][p][j] : make_float2(0.f, 0.f);
                    float c0 = fmaf(s.z, cold.x, s.x * tg0);
                    float c1 = fmaf(s.w, cold.y, s.y * tg1);
                    cst[l][p][j] = make_float2(c0, c1);
                    hst[l][p][j] = make_float2(so0 * tanh_(c0), so1 * tanh_(c1));
                }
            }
            __syncthreads();
        }
    }

    // =============== head: out[b] = sigmoid(h3[b].Wlin + blin) ===============
    float wl = gWlin[j];
    float bl = gBlin;
#pragma unroll
    for (int q = 0; q < 4; ++q) {
        int p = wb * 4 + q;
        float2 hv = hst[NL - 1][p][j];
        float s0 = hv.x * wl, s1 = hv.y * wl;
#pragma unroll
        for (int off = 16; off > 0; off >>= 1) {
            s0 += __shfl_xor_sync(0xffffffffu, s0, off);
            s1 += __shfl_xor_sync(0xffffffffu, s1, off);
        }
        if (j == 0) {
            out[base + 2 * p]     = sigm(s0 + bl);
            out[base + 2 * p + 1] = sigm(s1 + bl);
        }
    }
}

extern "C" void kernel_launch(void* const* d_in, const int* in_sizes, int n_in,
                              void* d_out, int out_size) {
    const float* x     = (const float*)d_in[0];
    const float* W_ih0 = (const float*)d_in[1];
    const float* W_ih  = (const float*)d_in[2];
    const float* W_hh  = (const float*)d_in[3];
    const float* b_ih  = (const float*)d_in[4];
    const float* b_hh  = (const float*)d_in[5];
    const float* W_lin = (const float*)d_in[6];
    const float* b_lin = (const float*)d_in[7];

    prep_kernel<<<32, 256>>>(W_ih0, W_ih, W_hh, b_ih, b_hh, W_lin, b_lin);

    int B = in_sizes[0] / (3 * TT);    // 16384
    int blocks = B / (NP * 2);         // 1024
    lstm_kernel<<<blocks, THREADS>>>(x, (float*)d_out);
}

// round 7
// speedup vs baseline: 6.5052x; 3.1014x over previous
#include <cuda_runtime.h>
#include <cuda_bf16.h>
#include <cstdint>

#define NL 4
#define TT 64
#define WARPS_CTA 7
#define ROWS_CTA (WARPS_CTA * 16)    // 112
#define THREADS (WARPS_CTA * 32)
#define BTOT 16384

// staged data (built by prep_kernel)
__device__ uint32_t gBF[32768];      // B fragments: [l][kc][nt][m][lane][word]  (128KB)
__device__ float    gBiasF[512];     // [l][nt][q][e]
__device__ float    gWl[32];
__device__ float    gBl;

// ---------------- helpers ----------------
__device__ __forceinline__ uint32_t smem_u32(const void* p) {
    uint32_t a;
    asm("{ .reg .u64 t; cvta.to.shared.u64 t, %1; cvt.u32.u64 %0, t; }" : "=r"(a) : "l"(p));
    return a;
}
__device__ __forceinline__ void mma16816(float d[4], const uint32_t a[4], uint32_t b0, uint32_t b1) {
    asm volatile("mma.sync.aligned.m16n8k16.row.col.f32.bf16.bf16.f32 "
                 "{%0,%1,%2,%3}, {%4,%5,%6,%7}, {%8,%9}, {%0,%1,%2,%3};"
                 : "+f"(d[0]), "+f"(d[1]), "+f"(d[2]), "+f"(d[3])
                 : "r"(a[0]), "r"(a[1]), "r"(a[2]), "r"(a[3]), "r"(b0), "r"(b1));
}
__device__ __forceinline__ void lds64(uint32_t& a, uint32_t& b, uint32_t addr) {
    asm volatile("ld.shared.v2.u32 {%0,%1}, [%2];" : "=r"(a), "=r"(b) : "r"(addr));
}
__device__ __forceinline__ float2 ldsf2(uint32_t addr) {
    float2 v;
    asm volatile("ld.shared.v2.f32 {%0,%1}, [%2];" : "=f"(v.x), "=f"(v.y) : "r"(addr));
    return v;
}
__device__ __forceinline__ float bfhi(float v) { return __bfloat162float(__float2bfloat16(v)); }
__device__ __forceinline__ uint32_t pkbf(float lo, float hi) {   // low half = lo
    __nv_bfloat162 t = __floats2bfloat162_rn(lo, hi);
    return *(uint32_t*)&t;
}
__device__ __forceinline__ float tanh_apx(float v) {
    float r; asm("tanh.approx.f32 %0, %1;" : "=f"(r) : "f"(v)); return r;
}
__device__ __forceinline__ float sigm_apx(float v) {             // i,f,o gates
    return fmaf(0.5f, tanh_apx(0.5f * v), 0.5f);
}
__device__ __forceinline__ float tanh_ex(float v) {              // g gate + tanh(c)
    return __fdividef(2.f, 1.f + __expf(-2.f * v)) - 1.f;
}
__device__ __forceinline__ float sigm_ex(float v) {
    return __fdividef(1.f, 1.f + __expf(-v));
}

// ---------------- prep ----------------
__device__ __forceinline__ float getW(const float* W_ih0, const float* W_ih, const float* W_hh,
                                      int l, int n, int k) {
    if (k < 32) {
        if (l == 0) return (k < 2) ? W_ih0[n * 2 + k] : 0.f;
        return W_ih[(l - 1) * 4096 + n * 32 + k];
    }
    return W_hh[l * 4096 + n * 32 + (k - 32)];
}

__global__ void prep_kernel(const float* __restrict__ W_ih0, const float* __restrict__ W_ih,
                            const float* __restrict__ W_hh, const float* __restrict__ b_ih,
                            const float* __restrict__ b_hh, const float* __restrict__ W_lin,
                            const float* __restrict__ b_lin) {
    int i = blockIdx.x * blockDim.x + threadIdx.x;
    if (i < 32768) {
        int word = i & 1, lane = (i >> 1) & 31, frag = i >> 6;
        int m = frag & 1, nt = (frag >> 1) & 15, kc = (frag >> 5) & 3, l = frag >> 7;
        int n  = nt * 8 + (lane >> 2);
        int k0 = kc * 16 + (lane & 3) * 2 + word * 8;
        float w0 = getW(W_ih0, W_ih, W_hh, l, n, k0);
        float w1 = getW(W_ih0, W_ih, W_hh, l, n, k0 + 1);
        float h0 = bfhi(w0), h1 = bfhi(w1);
        float v0 = (m == 0) ? h0 : (w0 - h0);
        float v1 = (m == 0) ? h1 : (w1 - h1);
        __nv_bfloat162 t = __floats2bfloat162_rn(v0, v1);
        gBF[i] = *(uint32_t*)&t;
    }
    if (i < 512) {
        int e = i & 1, q = (i >> 1) & 3, nt = (i >> 3) & 15, l = i >> 7;
        int n = nt * 8 + q * 2 + e;
        gBiasF[i] = b_ih[l * 128 + n] + b_hh[l * 128 + n];
    }
    if (i < 32) gWl[i] = W_lin[i];
    if (i == 0) gBl = b_lin[0];
}

// ---------------- mma over one k-chunk: 4 gate tiles, 3 terms ----------------
__device__ __forceinline__ void mma_chunk(float (&d)[4][4], const uint32_t* ahi, const uint32_t* alo,
                                          uint32_t bKC, int jt) {
#pragma unroll
    for (int g4 = 0; g4 < 4; ++g4) {
        uint32_t off = (uint32_t)((g4 * 4 + jt) * 2) * 256u;
        uint32_t bh0, bh1, bl0, bl1;
        lds64(bh0, bh1, bKC + off);         // Whi fragment
        lds64(bl0, bl1, bKC + off + 256);   // Wlo fragment
        mma16816(d[g4], ahi, bh0, bh1);
        mma16816(d[g4], alo, bh0, bh1);
        mma16816(d[g4], ahi, bl0, bl1);
    }
}

// ---------------- main kernel ----------------
__global__ void __launch_bounds__(THREADS, 1)
lstm_kernel(const float* __restrict__ x, float* __restrict__ out) {
    extern __shared__ __align__(16) uint4 smemraw[];
    const uint32_t smB   = smem_u32(smemraw);
    const uint32_t biasB = smB + 131072u;

    const int tid  = threadIdx.x;
    const int w    = tid >> 5;
    const int lane = tid & 31;
    const int q    = lane & 3;
    const int r    = lane >> 2;
    const int gb0  = blockIdx.x * ROWS_CTA + w * 16;

    // ---- stage B fragments + bias into SMEM ----
    {
        const uint4* src = (const uint4*)gBF;
        uint4* dst = (uint4*)smemraw;
        for (int i = tid; i < 8192; i += THREADS) dst[i] = src[i];
        float* bd = (float*)(smemraw + 8192);
        for (int i = tid; i < 512; i += THREADS) bd[i] = gBiasF[i];
    }
    __syncthreads();
    if (gb0 >= BTOT) return;

    // per-layer h fragments (bf16 hi/lo), this warp's 16 rows; chunk = 16 hidden cols
    uint32_t Ahi[NL][2][4], Alo[NL][2][4];
#pragma unroll
    for (int l = 0; l < NL; ++l)
#pragma unroll
        for (int ch = 0; ch < 2; ++ch)
#pragma unroll
            for (int rr = 0; rr < 4; ++rr) { Ahi[l][ch][rr] = 0u; Alo[l][ch][rr] = 0u; }

    float cst[NL][4][4];
#pragma unroll
    for (int l = 0; l < NL; ++l)
#pragma unroll
        for (int jt = 0; jt < 4; ++jt)
#pragma unroll
            for (int p = 0; p < 4; ++p) cst[l][jt][p] = 0.f;

    float wl[4][2];
#pragma unroll
    for (int jt = 0; jt < 4; ++jt) {
        wl[jt][0] = gWl[jt * 8 + q * 2];
        wl[jt][1] = gWl[jt * 8 + q * 2 + 1];
    }

    const float* xq  = x + (size_t)(gb0 + r) * 192;
    float prow0 = 0.f, prow8 = 0.f;
    const uint32_t laneOff = (uint32_t)lane * 8u;

#pragma unroll 1
    for (int t = 0; t < TT; ++t) {
        // ---- x fragment (layer 0, k-chunk 0): cols 0,1 live in q==0 lanes ----
        uint32_t axh[4] = {0u, 0u, 0u, 0u}, axl[4] = {0u, 0u, 0u, 0u};
        if (q == 0) {
            float x0a = __ldg(xq + t),            x1a = __ldg(xq + 64 + t);
            float x0b = __ldg(xq + 1536 + t),     x1b = __ldg(xq + 1600 + t);   // row+8
            float e0 = bfhi(x0a), e1 = bfhi(x1a), e2 = bfhi(x0b), e3 = bfhi(x1b);
            axh[0] = pkbf(e0, e1);            axh[1] = pkbf(e2, e3);
            axl[0] = pkbf(x0a - e0, x1a - e1); axl[1] = pkbf(x0b - e2, x1b - e3);
        }

        float hh[4][4];

#pragma unroll
        for (int l = 0; l < NL; ++l) {
#pragma unroll
            for (int jt = 0; jt < 4; ++jt) {
                // D init = bias
                float d[4][4];
#pragma unroll
                for (int g4 = 0; g4 < 4; ++g4) {
                    float2 bb = ldsf2(biasB + (uint32_t)(((l * 16 + g4 * 4 + jt) * 4 + q) * 8));
                    d[g4][0] = bb.x; d[g4][1] = bb.y; d[g4][2] = bb.x; d[g4][3] = bb.y;
                }
                // MMAs over k-chunks
                const uint32_t bL = smB + (uint32_t)(l * 4) * 8192u + laneOff;
                if (l == 0) {
                    mma_chunk(d, axh,          axl,          bL,             jt);  // x
                    mma_chunk(d, Ahi[0][0],    Alo[0][0],    bL + 2u * 8192u, jt); // h_prev lo-half
                    mma_chunk(d, Ahi[0][1],    Alo[0][1],    bL + 3u * 8192u, jt);
                } else {
                    mma_chunk(d, Ahi[l - 1][0], Alo[l - 1][0], bL,              jt); // h_in
                    mma_chunk(d, Ahi[l - 1][1], Alo[l - 1][1], bL + 1u * 8192u, jt);
                    mma_chunk(d, Ahi[l][0],     Alo[l][0],     bL + 2u * 8192u, jt); // h_prev
                    mma_chunk(d, Ahi[l][1],     Alo[l][1],     bL + 3u * 8192u, jt);
                }
                // cell epilogue (4 cells per thread per group)
#pragma unroll
                for (int p = 0; p < 4; ++p) {
                    float ii = sigm_apx(d[0][p]);
                    float ff = sigm_apx(d[1][p]);
                    float gg = tanh_ex(d[2][p]);
                    float oo = sigm_apx(d[3][p]);
                    float cn = fmaf(ff, cst[l][jt][p], ii * gg);
                    cst[l][jt][p] = cn;
                    float hv = oo * tanh_ex(cn);
                    hh[jt][p] = hv;
                    if (l == NL - 1 && t == TT - 1) {
                        if (p == 0) prow0 = fmaf(hv, wl[jt][0], prow0);
                        if (p == 1) prow0 = fmaf(hv, wl[jt][1], prow0);
                        if (p == 2) prow8 = fmaf(hv, wl[jt][0], prow8);
                        if (p == 3) prow8 = fmaf(hv, wl[jt][1], prow8);
                    }
                }
            }
            // rebuild this layer's A fragments from hh (bf16 hi/lo)
#pragma unroll
            for (int ch = 0; ch < 2; ++ch)
#pragma unroll
                for (int rr = 0; rr < 4; ++rr) {
                    int tile = ch * 2 + (rr >> 1);
                    int p0   = (rr & 1) * 2;
                    float h0 = hh[tile][p0], h1 = hh[tile][p0 + 1];
                    float e0 = bfhi(h0), e1 = bfhi(h1);
                    Ahi[l][ch][rr] = pkbf(e0, e1);
                    Alo[l][ch][rr] = pkbf(h0 - e0, h1 - e1);
                }
        }
    }

    // ---- head: out[row] = sigmoid(h3 . Wlin + b) ----
    prow0 += __shfl_xor_sync(0xffffffffu, prow0, 1);
    prow0 += __shfl_xor_sync(0xffffffffu, prow0, 2);
    prow8 += __shfl_xor_sync(0xffffffffu, prow8, 1);
    prow8 += __shfl_xor_sync(0xffffffffu, prow8, 2);
    if (q == 0) {
        float bl = gBl;
        out[gb0 + r]     = sigm_ex(prow0 + bl);
        out[gb0 + r + 8] = sigm_ex(prow8 + bl);
    }
}

extern "C" void kernel_launch(void* const* d_in, const int* in_sizes, int n_in,
                              void* d_out, int out_size) {
    const float* x     = (const float*)d_in[0];
    const float* W_ih0 = (const float*)d_in[1];
    const float* W_ih  = (const float*)d_in[2];
    const float* W_hh  = (const float*)d_in[3];
    const float* b_ih  = (const float*)d_in[4];
    const float* b_hh  = (const float*)d_in[5];
    const float* W_lin = (const float*)d_in[6];
    const float* b_lin = (const float*)d_in[7];

    prep_kernel<<<130, 256>>>(W_ih0, W_ih, W_hh, b_ih, b_hh, W_lin, b_lin);

    int dsm = 131072 + 2048 + 128;   // B frags + bias + pad
    cudaFuncSetAttribute(lstm_kernel, cudaFuncAttributeMaxDynamicSharedMemorySize, dsm);

    int blocks = (BTOT + ROWS_CTA - 1) / ROWS_CTA;    // 147
    lstm_kernel<<<blocks, THREADS, dsm>>>(x, (float*)d_out);
}

// round 8
// speedup vs baseline: 6.9341x; 1.0659x over previous
#include <cuda_runtime.h>
#include <cuda_bf16.h>
#include <cstdint>

#define NL 4
#define TT 64
#define PAIRS 7
#define THREADS (PAIRS * 64)         // 448: 7 warp pairs
#define ROWS_CTA (PAIRS * 16)        // 112
#define BTOT 16384

// SMEM offsets (dynamic)
#define OFF_BIAS 131072u
#define OFF_HX   133120u             // PAIRS*NL*2 chunks * 1KB = 57344
#define OFF_RED  190464u             // PAIRS*2*16 floats
#define DSMEM    (190464 + 896 + 64)

// staged data (built by prep_kernel)
__device__ uint32_t gBF[32768];      // B fragments [l][kc][nt][m][lane][word] (128KB)
__device__ float    gBiasF[512];
__device__ float    gWl[32];
__device__ float    gBl;

// ---------------- helpers ----------------
__device__ __forceinline__ uint32_t smem_u32(const void* p) {
    uint32_t a;
    asm("{ .reg .u64 t; cvta.to.shared.u64 t, %1; cvt.u32.u64 %0, t; }" : "=r"(a) : "l"(p));
    return a;
}
__device__ __forceinline__ void mma16816(float d[4], const uint32_t a[4], uint32_t b0, uint32_t b1) {
    asm volatile("mma.sync.aligned.m16n8k16.row.col.f32.bf16.bf16.f32 "
                 "{%0,%1,%2,%3}, {%4,%5,%6,%7}, {%8,%9}, {%0,%1,%2,%3};"
                 : "+f"(d[0]), "+f"(d[1]), "+f"(d[2]), "+f"(d[3])
                 : "r"(a[0]), "r"(a[1]), "r"(a[2]), "r"(a[3]), "r"(b0), "r"(b1));
}
__device__ __forceinline__ void lds64(uint32_t& a, uint32_t& b, uint32_t addr) {
    asm volatile("ld.shared.v2.u32 {%0,%1}, [%2];" : "=r"(a), "=r"(b) : "r"(addr));
}
__device__ __forceinline__ float2 ldsf2(uint32_t addr) {
    float2 v;
    asm volatile("ld.shared.v2.f32 {%0,%1}, [%2];" : "=f"(v.x), "=f"(v.y) : "r"(addr));
    return v;
}
__device__ __forceinline__ void ld8(uint32_t* f, uint32_t addr) {
    asm volatile("ld.shared.v4.u32 {%0,%1,%2,%3}, [%4];"
                 : "=r"(f[0]), "=r"(f[1]), "=r"(f[2]), "=r"(f[3]) : "r"(addr));
    asm volatile("ld.shared.v4.u32 {%0,%1,%2,%3}, [%4];"
                 : "=r"(f[4]), "=r"(f[5]), "=r"(f[6]), "=r"(f[7]) : "r"(addr + 16u));
}
__device__ __forceinline__ void st8(uint32_t addr, const uint32_t* f) {
    asm volatile("st.shared.v4.u32 [%0], {%1,%2,%3,%4};"
                 :: "r"(addr), "r"(f[0]), "r"(f[1]), "r"(f[2]), "r"(f[3]) : "memory");
    asm volatile("st.shared.v4.u32 [%0], {%1,%2,%3,%4};"
                 :: "r"(addr + 16u), "r"(f[4]), "r"(f[5]), "r"(f[6]), "r"(f[7]) : "memory");
}
__device__ __forceinline__ void stsf(uint32_t addr, float v) {
    asm volatile("st.shared.f32 [%0], %1;" :: "r"(addr), "f"(v) : "memory");
}
__device__ __forceinline__ float ldsf(uint32_t addr) {
    float v; asm volatile("ld.shared.f32 %0, [%1];" : "=f"(v) : "r"(addr)); return v;
}
#define BARP(id) asm volatile("bar.sync %0, 64;" :: "r"(id) : "memory")

__device__ __forceinline__ float bfhi(float v) { return __bfloat162float(__float2bfloat16(v)); }
__device__ __forceinline__ uint32_t pkbf(float lo, float hi) {
    __nv_bfloat162 t = __floats2bfloat162_rn(lo, hi);
    return *(uint32_t*)&t;
}
__device__ __forceinline__ float tanh_apx(float v) {
    float r; asm("tanh.approx.f32 %0, %1;" : "=f"(r) : "f"(v)); return r;
}
__device__ __forceinline__ float sigm_apx(float v) {
    return fmaf(0.5f, tanh_apx(0.5f * v), 0.5f);
}
__device__ __forceinline__ float sigm_ex(float v) {
    return __fdividef(1.f, 1.f + __expf(-v));
}

// ---------------- prep (identical to R7) ----------------
__device__ __forceinline__ float getW(const float* W_ih0, const float* W_ih, const float* W_hh,
                                      int l, int n, int k) {
    if (k < 32) {
        if (l == 0) return (k < 2) ? W_ih0[n * 2 + k] : 0.f;
        return W_ih[(l - 1) * 4096 + n * 32 + k];
    }
    return W_hh[l * 4096 + n * 32 + (k - 32)];
}

__global__ void prep_kernel(const float* __restrict__ W_ih0, const float* __restrict__ W_ih,
                            const float* __restrict__ W_hh, const float* __restrict__ b_ih,
                            const float* __restrict__ b_hh, const float* __restrict__ W_lin,
                            const float* __restrict__ b_lin) {
    int i = blockIdx.x * blockDim.x + threadIdx.x;
    if (i < 32768) {
        int word = i & 1, lane = (i >> 1) & 31, frag = i >> 6;
        int m = frag & 1, nt = (frag >> 1) & 15, kc = (frag >> 5) & 3, l = frag >> 7;
        int n  = nt * 8 + (lane >> 2);
        int k0 = kc * 16 + (lane & 3) * 2 + word * 8;
        float w0 = getW(W_ih0, W_ih, W_hh, l, n, k0);
        float w1 = getW(W_ih0, W_ih, W_hh, l, n, k0 + 1);
        float h0 = bfhi(w0), h1 = bfhi(w1);
        float v0 = (m == 0) ? h0 : (w0 - h0);
        float v1 = (m == 0) ? h1 : (w1 - h1);
        __nv_bfloat162 t = __floats2bfloat162_rn(v0, v1);
        gBF[i] = *(uint32_t*)&t;
    }
    if (i < 512) {
        int e = i & 1, q = (i >> 1) & 3, nt = (i >> 3) & 15, l = i >> 7;
        int n = nt * 8 + q * 2 + e;
        gBiasF[i] = b_ih[l * 128 + n] + b_hh[l * 128 + n];
    }
    if (i < 32) gWl[i] = W_lin[i];
    if (i == 0) gBl = b_lin[0];
}

// ---------------- one k-chunk: 4 gate tiles, 3-term bf16 emulation ----------------
__device__ __forceinline__ void mma_chunk(float (&d)[4][4], const uint32_t* ahi, const uint32_t* alo,
                                          uint32_t bKC, int jt) {
#pragma unroll
    for (int g4 = 0; g4 < 4; ++g4) {
        uint32_t off = (uint32_t)((g4 * 4 + jt) * 2) * 256u;
        uint32_t bh0, bh1, bl0, bl1;
        lds64(bh0, bh1, bKC + off);
        lds64(bl0, bl1, bKC + off + 256);
        mma16816(d[g4], ahi, bh0, bh1);
        mma16816(d[g4], alo, bh0, bh1);
        mma16816(d[g4], ahi, bl0, bl1);
    }
}

// ---------------- main kernel ----------------
__global__ void __launch_bounds__(THREADS, 1)
lstm_kernel(const float* __restrict__ x, float* __restrict__ out) {
    extern __shared__ __align__(16) uint4 smemraw[];
    const uint32_t smB   = smem_u32(smemraw);
    const uint32_t biasB = smB + OFF_BIAS;
    const uint32_t hxB   = smB + OFF_HX;
    const uint32_t redB  = smB + OFF_RED;

    const int tid  = threadIdx.x;
    const int w    = tid >> 5;
    const int lane = tid & 31;
    const int q    = lane & 3;
    const int r    = lane >> 2;
    const int pp   = w >> 1;            // pair id
    const int wh   = w & 1;             // half: gate cols [16wh,16wh+16), owns h chunk wh
    const int bid  = 1 + pp;            // named barrier id
    const int gb0  = blockIdx.x * ROWS_CTA + pp * 16;

    // ---- stage weights + bias; zero hx ----
    {
        const uint4* src = (const uint4*)gBF;
        uint4* dst = (uint4*)smemraw;
        for (int i = tid; i < 8192; i += THREADS) dst[i] = src[i];
        float* bd = (float*)((char*)smemraw + OFF_BIAS);
        for (int i = tid; i < 512; i += THREADS) bd[i] = gBiasF[i];
        uint4* hz = (uint4*)((char*)smemraw + OFF_HX);
        for (int i = tid; i < 57344 / 16; i += THREADS) hz[i] = make_uint4(0, 0, 0, 0);
    }
    __syncthreads();
    if (gb0 >= BTOT) return;

    float cst[NL][2][4];
#pragma unroll
    for (int l = 0; l < NL; ++l)
#pragma unroll
        for (int jl = 0; jl < 2; ++jl)
#pragma unroll
            for (int p = 0; p < 4; ++p) cst[l][jl][p] = 0.f;

    float wl[2][2];
#pragma unroll
    for (int jl = 0; jl < 2; ++jl) {
        int jt = wh * 2 + jl;
        wl[jl][0] = gWl[jt * 8 + q * 2];
        wl[jl][1] = gWl[jt * 8 + q * 2 + 1];
    }

    const float* xq = x + (size_t)(gb0 + r) * 192;
    float prow0 = 0.f, prow8 = 0.f;
    const uint32_t laneOff = (uint32_t)lane * 8u;
    const uint32_t hxPair  = hxB + (uint32_t)(pp * NL * 2) * 1024u + (uint32_t)lane * 32u;

#pragma unroll 1
    for (int t = 0; t < TT; ++t) {
        // ---- x fragment (layer 0, k-chunk 0): cols 0,1 live in q==0 lanes ----
        uint32_t axh[4] = {0u, 0u, 0u, 0u}, axl[4] = {0u, 0u, 0u, 0u};
        if (q == 0) {
            float x0a = __ldg(xq + t),        x1a = __ldg(xq + 64 + t);
            float x0b = __ldg(xq + 1536 + t), x1b = __ldg(xq + 1600 + t);   // row+8
            float e0 = bfhi(x0a), e1 = bfhi(x1a), e2 = bfhi(x0b), e3 = bfhi(x1b);
            axh[0] = pkbf(e0, e1);             axh[1] = pkbf(e2, e3);
            axl[0] = pkbf(x0a - e0, x1a - e1); axl[1] = pkbf(x0b - e2, x1b - e3);
        }

#pragma unroll
        for (int l = 0; l < NL; ++l) {
            const uint32_t hxL = hxPair + (uint32_t)(l * 2) * 1024u;
            uint32_t hin0[8], hin1[8], hp0[8], hp1[8];
            if (l > 0) {
                ld8(hin0, hxL - 2048u);
                ld8(hin1, hxL - 1024u);
            }
            ld8(hp0, hxL);
            ld8(hp1, hxL + 1024u);

            float hh[2][4];
#pragma unroll
            for (int jl = 0; jl < 2; ++jl) {
                const int jt = wh * 2 + jl;
                float d[4][4];
#pragma unroll
                for (int g4 = 0; g4 < 4; ++g4) {
                    float2 bb = ldsf2(biasB + (uint32_t)(((l * 16 + g4 * 4 + jt) * 4 + q) * 8));
                    d[g4][0] = bb.x; d[g4][1] = bb.y; d[g4][2] = bb.x; d[g4][3] = bb.y;
                }
                const uint32_t bL = smB + (uint32_t)l * 32768u + laneOff;
                if (l == 0) {
                    mma_chunk(d, axh, axl, bL, jt);                       // x (kc0)
                } else {
                    mma_chunk(d, hin0, hin0 + 4, bL,          jt);        // h_in kc0
                    mma_chunk(d, hin1, hin1 + 4, bL + 8192u,  jt);        // h_in kc1
                }
                mma_chunk(d, hp0, hp0 + 4, bL + 16384u, jt);              // h_prev kc2
                mma_chunk(d, hp1, hp1 + 4, bL + 24576u, jt);              // h_prev kc3

#pragma unroll
                for (int p = 0; p < 4; ++p) {
                    float ii = sigm_apx(d[0][p]);
                    float ff = sigm_apx(d[1][p]);
                    float gg = tanh_apx(d[2][p]);
                    float oo = sigm_apx(d[3][p]);
                    float cn = fmaf(ff, cst[l][jl][p], ii * gg);
                    cst[l][jl][p] = cn;
                    float hv = oo * tanh_apx(cn);
                    hh[jl][p] = hv;
                    if (l == NL - 1 && t == TT - 1) {
                        if (p == 0) prow0 = fmaf(hv, wl[jl][0], prow0);
                        if (p == 1) prow0 = fmaf(hv, wl[jl][1], prow0);
                        if (p == 2) prow8 = fmaf(hv, wl[jl][0], prow8);
                        if (p == 3) prow8 = fmaf(hv, wl[jl][1], prow8);
                    }
                }
            }

            BARP(bid);   // partner finished reading hx[l] (h_prev)
            uint32_t fr[8];
#pragma unroll
            for (int rr = 0; rr < 4; ++rr) {
                int jl = rr >> 1, p0 = (rr & 1) * 2;
                float h0 = hh[jl][p0], h1 = hh[jl][p0 + 1];
                float e0 = bfhi(h0), e1 = bfhi(h1);
                fr[rr]     = pkbf(e0, e1);
                fr[4 + rr] = pkbf(h0 - e0, h1 - e1);
            }
            st8(hxL + (uint32_t)wh * 1024u, fr);
            BARP(bid);   // publish h_new for next layer / next step
        }
    }

    // ---- head: out = sigmoid(h3 . Wlin + b) ----
    prow0 += __shfl_xor_sync(0xffffffffu, prow0, 1);
    prow0 += __shfl_xor_sync(0xffffffffu, prow0, 2);
    prow8 += __shfl_xor_sync(0xffffffffu, prow8, 1);
    prow8 += __shfl_xor_sync(0xffffffffu, prow8, 2);
    const uint32_t redP = redB + (uint32_t)((pp * 2 + wh) * 64);
    if (q == 0) {
        stsf(redP + (uint32_t)r * 4, prow0);
        stsf(redP + (uint32_t)(r + 8) * 4, prow8);
    }
    BARP(bid);
    if (wh == 0 && q == 0) {
        float bl = gBl;
        float v0 = ldsf(redP + (uint32_t)r * 4)       + ldsf(redP + 64u + (uint32_t)r * 4);
        float v8 = ldsf(redP + (uint32_t)(r + 8) * 4) + ldsf(redP + 64u + (uint32_t)(r + 8) * 4);
        out[gb0 + r]     = sigm_ex(v0 + bl);
        out[gb0 + r + 8] = sigm_ex(v8 + bl);
    }
}

extern "C" void kernel_launch(void* const* d_in, const int* in_sizes, int n_in,
                              void* d_out, int out_size) {
    const float* x     = (const float*)d_in[0];
    const float* W_ih0 = (const float*)d_in[1];
    const float* W_ih  = (const float*)d_in[2];
    const float* W_hh  = (const float*)d_in[3];
    const float* b_ih  = (const float*)d_in[4];
    const float* b_hh  = (const float*)d_in[5];
    const float* W_lin = (const float*)d_in[6];
    const float* b_lin = (const float*)d_in[7];

    prep_kernel<<<130, 256>>>(W_ih0, W_ih, W_hh, b_ih, b_hh, W_lin, b_lin);

    cudaFuncSetAttribute(lstm_kernel, cudaFuncAttributeMaxDynamicSharedMemorySize, DSMEM);

    int blocks = (BTOT + ROWS_CTA - 1) / ROWS_CTA;    // 147
    lstm_kernel<<<blocks, THREADS, DSMEM>>>(x, (float*)d_out);
}